// round 2
// baseline (speedup 1.0000x reference)
#include <cuda_runtime.h>
#include <math.h>

#define TT 2048
#define DD 1024
#define NH 8
#define HD 128
#define KC 4
#define CH 64
#define NCHUNK (TT / CH)
#define ATT_SCALE 0.08838834764831845f  // 1/sqrt(128)

// ---------------- scratch (device globals; no allocation allowed) ----------
__device__ float g_raw[4 * TT * DD];          // Qraw, Kraw, Vraw, Wpre
__device__ float g_q[NH * TT * HD];           // [h][t][d] rms-normed
__device__ float g_k[NH * TT * HD];
__device__ float g_v[NH * TT * HD];
__device__ float g_w[NH * TT * HD];           // householder dirs, unit norm
__device__ float g_beta[NH * TT];
__device__ float g_gpre[NH * TT];
__device__ float g_G[NH * TT];
__device__ float g_A[(size_t)NH * TT * TT];   // QK^T -> logits -> P
__device__ float g_QW[(size_t)NH * TT * TT];  // tril(q w^T, 0)
__device__ float g_Mw[(size_t)NH * TT * TT];  // strict-lower (w w^T)*beta_col
__device__ float g_bm[(size_t)NH * TT * TT];  // rhs -> bmat -> btil
__device__ float g_O[TT * DD];                // P@V in [t, h*128+d] layout

// ---------------- generic fp32 GEMM: C (=|-=) A@B ---------------------------
// 64x64 tile, BK=16, 256 threads, 4x4 micro-tile. M from gridDim.y, N from
// gridDim.x (all dims multiples of 64/16 by construction). z-dim strides for
// batching over heads.
__global__ __launch_bounds__(256) void gemm_f32(
    const float* __restrict__ A, const float* __restrict__ B, float* __restrict__ C,
    int K, int lda, int ldb, int ldc,
    long long sA, long long sB, long long sC, int subAcc)
{
    A += (long long)blockIdx.z * sA;
    B += (long long)blockIdx.z * sB;
    C += (long long)blockIdx.z * sC;
    const int rowBase = blockIdx.y * 64;
    const int colBase = blockIdx.x * 64;
    const int tid = threadIdx.x;
    const int tx = tid & 15, ty = tid >> 4;
    __shared__ float As[16][68];
    __shared__ float Bs[16][68];
    float acc[4][4] = {};
    const int ra = tid >> 2, pa = (tid & 3) << 2;
    const int pb = tid >> 4, cb = (tid & 15) << 2;
    for (int kk = 0; kk < K; kk += 16) {
        float4 av = *(const float4*)(A + (long long)(rowBase + ra) * lda + kk + pa);
        As[pa + 0][ra] = av.x; As[pa + 1][ra] = av.y;
        As[pa + 2][ra] = av.z; As[pa + 3][ra] = av.w;
        float4 bv = *(const float4*)(B + (long long)(kk + pb) * ldb + colBase + cb);
        *(float4*)&Bs[pb][cb] = bv;
        __syncthreads();
#pragma unroll
        for (int p = 0; p < 16; p++) {
            float4 a4 = *(const float4*)&As[p][ty * 4];
            float4 b4 = *(const float4*)&Bs[p][tx * 4];
            float a[4] = {a4.x, a4.y, a4.z, a4.w};
            float b[4] = {b4.x, b4.y, b4.z, b4.w};
#pragma unroll
            for (int i = 0; i < 4; i++)
#pragma unroll
                for (int j = 0; j < 4; j++) acc[i][j] += a[i] * b[j];
        }
        __syncthreads();
    }
#pragma unroll
    for (int i = 0; i < 4; i++) {
        float* cp = C + (long long)(rowBase + ty * 4 + i) * ldc + colBase + tx * 4;
        if (subAcc) {
            float4 cv = *(const float4*)cp;
            cv.x -= acc[i][0]; cv.y -= acc[i][1];
            cv.z -= acc[i][2]; cv.w -= acc[i][3];
            *(float4*)cp = cv;
        } else {
            float4 cv = {acc[i][0], acc[i][1], acc[i][2], acc[i][3]};
            *(float4*)cp = cv;
        }
    }
}

// ---------------- head-batched C = A @ B^T for [T,128] operands -------------
// modes: 0 = QK^T plain (skip strictly-above-diag tiles)
//        1 = QW^T masked j<=t (skip above-diag tiles; they're never read)
//        2 = WK^T strict lower (above-diag tiles explicitly zeroed)
//        3 = (WW^T)*beta[col], strict lower (skip above-diag tiles)
__global__ __launch_bounds__(256) void gemm_nt(
    const float* __restrict__ Aten, const float* __restrict__ Bten,
    float* __restrict__ C, const float* __restrict__ betaArr, int mode)
{
    const int bx = blockIdx.x, by = blockIdx.y, h = blockIdx.z;
    const int tid = threadIdx.x;
    const int tx = tid & 15, ty = tid >> 4;
    const int rowBase = by * 64, colBase = bx * 64;
    float* Ch = C + (size_t)h * TT * TT;
    if (bx > by) {
        if (mode == 2) {
            float4 z = {0.f, 0.f, 0.f, 0.f};
#pragma unroll
            for (int i = 0; i < 4; i++)
                *(float4*)(Ch + (size_t)(rowBase + ty * 4 + i) * TT + colBase + tx * 4) = z;
        }
        return;
    }
    const float* A = Aten + (size_t)h * TT * HD;
    const float* B = Bten + (size_t)h * TT * HD;
    __shared__ float As[16][68];
    __shared__ float Bs[16][68];
    float acc[4][4] = {};
    const int ra = tid >> 2, pa = (tid & 3) << 2;
    for (int kk = 0; kk < HD; kk += 16) {
        float4 av = *(const float4*)(A + (size_t)(rowBase + ra) * HD + kk + pa);
        As[pa + 0][ra] = av.x; As[pa + 1][ra] = av.y;
        As[pa + 2][ra] = av.z; As[pa + 3][ra] = av.w;
        float4 bv = *(const float4*)(B + (size_t)(colBase + ra) * HD + kk + pa);
        Bs[pa + 0][ra] = bv.x; Bs[pa + 1][ra] = bv.y;
        Bs[pa + 2][ra] = bv.z; Bs[pa + 3][ra] = bv.w;
        __syncthreads();
#pragma unroll
        for (int p = 0; p < 16; p++) {
            float4 a4 = *(const float4*)&As[p][ty * 4];
            float4 b4 = *(const float4*)&Bs[p][tx * 4];
            float a[4] = {a4.x, a4.y, a4.z, a4.w};
            float b[4] = {b4.x, b4.y, b4.z, b4.w};
#pragma unroll
            for (int i = 0; i < 4; i++)
#pragma unroll
                for (int j = 0; j < 4; j++) acc[i][j] += a[i] * b[j];
        }
        __syncthreads();
    }
#pragma unroll
    for (int i = 0; i < 4; i++) {
        int t = rowBase + ty * 4 + i;
#pragma unroll
        for (int j = 0; j < 4; j++) {
            int jj = colBase + tx * 4 + j;
            float v = acc[i][j];
            if (mode == 1)      v = (jj <= t) ? v : 0.0f;
            else if (mode == 2) v = (jj < t) ? v : 0.0f;
            else if (mode == 3) v = (jj < t) ? v * betaArr[h * TT + jj] : 0.0f;
            Ch[(size_t)t * TT + jj] = v;
        }
    }
}

// ---------------- A -= tril(QW) @ btil, lower-triangle tiles only -----------
// Inner s runs [colBase, rowBase+64); stored masks supply zeros outside (j,t].
__global__ __launch_bounds__(256) void tri_update()
{
    const int bx = blockIdx.x, by = blockIdx.y, h = blockIdx.z;
    if (bx > by) return;
    const float* Ah = g_QW + (size_t)h * TT * TT;
    const float* Bh = g_bm + (size_t)h * TT * TT;
    float* Ch = g_A + (size_t)h * TT * TT;
    const int rowBase = by * 64, colBase = bx * 64;
    const int tid = threadIdx.x;
    const int tx = tid & 15, ty = tid >> 4;
    __shared__ float As[16][68];
    __shared__ float Bs[16][68];
    float acc[4][4] = {};
    const int ra = tid >> 2, pa = (tid & 3) << 2;
    const int pb = tid >> 4, cb = (tid & 15) << 2;
    const int kEnd = rowBase + 64;
    for (int kk = colBase; kk < kEnd; kk += 16) {
        float4 av = *(const float4*)(Ah + (size_t)(rowBase + ra) * TT + kk + pa);
        As[pa + 0][ra] = av.x; As[pa + 1][ra] = av.y;
        As[pa + 2][ra] = av.z; As[pa + 3][ra] = av.w;
        float4 bv = *(const float4*)(Bh + (size_t)(kk + pb) * TT + colBase + cb);
        *(float4*)&Bs[pb][cb] = bv;
        __syncthreads();
#pragma unroll
        for (int p = 0; p < 16; p++) {
            float4 a4 = *(const float4*)&As[p][ty * 4];
            float4 b4 = *(const float4*)&Bs[p][tx * 4];
            float a[4] = {a4.x, a4.y, a4.z, a4.w};
            float b[4] = {b4.x, b4.y, b4.z, b4.w};
#pragma unroll
            for (int i = 0; i < 4; i++)
#pragma unroll
                for (int j = 0; j < 4; j++) acc[i][j] += a[i] * b[j];
        }
        __syncthreads();
    }
#pragma unroll
    for (int i = 0; i < 4; i++) {
        float* cp = Ch + (size_t)(rowBase + ty * 4 + i) * TT + colBase + tx * 4;
        float4 cv = *(const float4*)cp;
        cv.x -= acc[i][0]; cv.y -= acc[i][1];
        cv.z -= acc[i][2]; cv.w -= acc[i][3];
        *(float4*)cp = cv;
    }
}

// ---------------- in-chunk forward substitution (columns independent) -------
__global__ void chunk_solve(int chunk)
{
    const int h = blockIdx.z;
    const float* Mh = g_Mw + (size_t)h * TT * TT;
    float* bh = g_bm + (size_t)h * TT * TT;
    const int rowBase = chunk * CH;
    const int tid = threadIdx.x;            // 64 threads, one column each
    const int j = blockIdx.x * CH + tid;
    __shared__ float Ms[CH][CH + 1];
    __shared__ float bs[CH][CH + 1];
    for (int r = 0; r < CH; r++) {
        Ms[r][tid] = Mh[(size_t)(rowBase + r) * TT + rowBase + tid];
        bs[r][tid] = bh[(size_t)(rowBase + r) * TT + j];
    }
    __syncthreads();
    for (int r = 1; r < CH; r++) {
        float sum = 0.0f;
        for (int s = 0; s < r; s++) sum += Ms[r][s] * bs[s][tid];
        bs[r][tid] -= sum;
    }
    for (int r = 0; r < CH; r++)
        bh[(size_t)(rowBase + r) * TT + j] = bs[r][tid];
}

// ---------------- btil = beta_row * bmat (rows scale) ------------------------
__global__ void scale_btil()
{
    size_t idx = (size_t)blockIdx.x * blockDim.x + threadIdx.x;
    size_t row = idx / TT;                  // == h*TT + t
    g_bm[idx] *= g_beta[row];
}

// ---------------- prep: rms(q,k), v copy, conv+silu+l2norm w ----------------
__device__ __forceinline__ float block_reduce_128(float v, float* sh)
{
    int tid = threadIdx.x;
    sh[tid] = v; __syncthreads();
    for (int s = 64; s > 0; s >>= 1) {
        if (tid < s) sh[tid] += sh[tid + s];
        __syncthreads();
    }
    float r = sh[0]; __syncthreads();
    return r;
}

__global__ void prep_kernel(const float* __restrict__ qn_w,
                            const float* __restrict__ kn_w,
                            const float* __restrict__ convw)
{
    const int t = blockIdx.x, h = blockIdx.y, i = threadIdx.x;
    __shared__ float sh[128];
    const float* Qr = g_raw;
    const float* Kr = g_raw + (size_t)TT * DD;
    const float* Vr = g_raw + (size_t)2 * TT * DD;
    const float* Wp = g_raw + (size_t)3 * TT * DD;
    const int col = h * HD + i;
    const size_t out = ((size_t)h * TT + t) * HD + i;

    float qv = Qr[(size_t)t * DD + col];
    float s = block_reduce_128(qv * qv, sh);
    g_q[out] = qv * rsqrtf(s * (1.0f / HD) + 1e-6f) * qn_w[i];

    float kv = Kr[(size_t)t * DD + col];
    s = block_reduce_128(kv * kv, sh);
    g_k[out] = kv * rsqrtf(s * (1.0f / HD) + 1e-6f) * kn_w[i];

    g_v[out] = Vr[(size_t)t * DD + col];

    float wc = 0.0f;
#pragma unroll
    for (int tap = 0; tap < KC; tap++) {
        int tt = t - (KC - 1) + tap;
        if (tt >= 0) wc += Wp[(size_t)tt * DD + col] * convw[col * KC + tap];
    }
    wc = wc / (1.0f + __expf(-wc));         // silu
    s = block_reduce_128(wc * wc, sh);
    g_w[out] = wc * rsqrtf(s + 1e-6f);
}

// ---------------- beta = 2*sigmoid(x@Wbeta), gpre = x@Wg --------------------
__global__ void betag_kernel(const float* __restrict__ x,
                             const float* __restrict__ Wbeta,
                             const float* __restrict__ Wg)
{
    const int t = blockIdx.x;
    const int tid = threadIdx.x;
    const int wid = tid >> 5, lane = tid & 31;   // 8 warps = 8 heads
    const float* xr = x + (size_t)t * DD;
    float sb = 0.0f, sg = 0.0f;
    for (int dd = lane; dd < DD; dd += 32) {
        float xv = xr[dd];
        sb += xv * Wbeta[dd * NH + wid];
        sg += xv * Wg[dd * NH + wid];
    }
#pragma unroll
    for (int o = 16; o > 0; o >>= 1) {
        sb += __shfl_down_sync(0xffffffffu, sb, o);
        sg += __shfl_down_sync(0xffffffffu, sg, o);
    }
    if (lane == 0) {
        g_beta[wid * TT + t] = 2.0f / (1.0f + __expf(-sb));
        g_gpre[wid * TT + t] = sg;
    }
}

// ---------------- G = cumsum(log_sigmoid(gpre)) over t ----------------------
__global__ void cumsum_kernel()
{
    int h = threadIdx.x;
    if (h >= NH) return;
    float run = 0.0f;
    for (int t = 0; t < TT; t++) {
        float x = g_gpre[h * TT + t];
        float ls = fminf(x, 0.0f) - log1pf(__expf(-fabsf(x)));
        run += ls;
        g_G[h * TT + t] = run;
    }
}

// ---------------- masked softmax with FoX gates; zero the upper triangle ----
__global__ void softmax_kernel()
{
    const int t = blockIdx.x, h = blockIdx.y;
    float* row = g_A + ((size_t)h * TT + t) * TT;
    const float* Gh = g_G + h * TT;
    const float Gt = Gh[t];
    const int n = t + 1;
    const int tid = threadIdx.x;
    __shared__ float red[256];

    float m = -1e30f;
    for (int j = tid; j < n; j += 256) {
        float l = row[j] * ATT_SCALE + Gt - Gh[j];
        m = fmaxf(m, l);
    }
    red[tid] = m; __syncthreads();
    for (int s = 128; s > 0; s >>= 1) {
        if (tid < s) red[tid] = fmaxf(red[tid], red[tid + s]);
        __syncthreads();
    }
    m = red[0]; __syncthreads();

    float sum = 0.0f;
    for (int j = tid; j < n; j += 256) {
        float l = row[j] * ATT_SCALE + Gt - Gh[j];
        sum += __expf(l - m);
    }
    red[tid] = sum; __syncthreads();
    for (int s = 128; s > 0; s >>= 1) {
        if (tid < s) red[tid] += red[tid + s];
        __syncthreads();
    }
    const float inv = 1.0f / red[0];

    for (int j = tid; j < n; j += 256) {
        float l = row[j] * ATT_SCALE + Gt - Gh[j];
        row[j] = __expf(l - m) * inv;
    }
    for (int j = n + tid; j < TT; j += 256) row[j] = 0.0f;
}

// ---------------------------------------------------------------------------
extern "C" void kernel_launch(void* const* d_in, const int* in_sizes, int n_in,
                              void* d_out, int out_size)
{
    const float* x     = (const float*)d_in[0];
    const float* Wq    = (const float*)d_in[1];
    const float* Wk    = (const float*)d_in[2];
    const float* Wv    = (const float*)d_in[3];
    const float* Ww    = (const float*)d_in[4];
    const float* Wbeta = (const float*)d_in[5];
    const float* Wg    = (const float*)d_in[6];
    const float* Wo    = (const float*)d_in[7];
    const float* convw = (const float*)d_in[8];
    const float* qnw   = (const float*)d_in[9];
    const float* knw   = (const float*)d_in[10];
    float* out = (float*)d_out;

    float *raw, *q, *k, *v, *w, *A, *QW, *Mw, *bm, *O, *beta;
    cudaGetSymbolAddress((void**)&raw, g_raw);
    cudaGetSymbolAddress((void**)&q, g_q);
    cudaGetSymbolAddress((void**)&k, g_k);
    cudaGetSymbolAddress((void**)&v, g_v);
    cudaGetSymbolAddress((void**)&w, g_w);
    cudaGetSymbolAddress((void**)&A, g_A);
    cudaGetSymbolAddress((void**)&QW, g_QW);
    cudaGetSymbolAddress((void**)&Mw, g_Mw);
    cudaGetSymbolAddress((void**)&bm, g_bm);
    cudaGetSymbolAddress((void**)&O, g_O);
    cudaGetSymbolAddress((void**)&beta, g_beta);

    const dim3 gProj(DD / 64, TT / 64, 1);
    // Q, K, V, Wpre projections
    gemm_f32<<<gProj, 256>>>(x, Wq, raw + (size_t)0 * TT * DD, DD, DD, DD, DD, 0, 0, 0, 0);
    gemm_f32<<<gProj, 256>>>(x, Wk, raw + (size_t)1 * TT * DD, DD, DD, DD, DD, 0, 0, 0, 0);
    gemm_f32<<<gProj, 256>>>(x, Wv, raw + (size_t)2 * TT * DD, DD, DD, DD, DD, 0, 0, 0, 0);
    gemm_f32<<<gProj, 256>>>(x, Ww, raw + (size_t)3 * TT * DD, DD, DD, DD, DD, 0, 0, 0, 0);

    betag_kernel<<<TT, 256>>>(x, Wbeta, Wg);
    cumsum_kernel<<<1, 32>>>();
    prep_kernel<<<dim3(TT, NH), 128>>>(qnw, knw, convw);

    const dim3 gNT(TT / 64, TT / 64, NH);
    gemm_nt<<<gNT, 256>>>(q, k, A, nullptr, 0);    // QK^T (lower)
    gemm_nt<<<gNT, 256>>>(q, w, QW, nullptr, 1);   // tril(QW^T, 0)
    gemm_nt<<<gNT, 256>>>(w, k, bm, nullptr, 2);   // rhs = tril(WK^T, -1)
    gemm_nt<<<gNT, 256>>>(w, w, Mw, beta, 3);      // strict-lower (WW^T)*beta_col

    // blocked forward substitution: M bmat = rhs
    chunk_solve<<<dim3(1, 1, NH), CH>>>(0);
    for (int c = 1; c < NCHUNK; c++) {
        gemm_f32<<<dim3(c, 1, NH), 256>>>(
            Mw + (size_t)c * CH * TT, bm, bm + (size_t)c * CH * TT,
            c * CH, TT, TT, TT,
            (long long)TT * TT, (long long)TT * TT, (long long)TT * TT, 1);
        chunk_solve<<<dim3(c + 1, 1, NH), CH>>>(c);
    }

    scale_btil<<<(unsigned)(((size_t)NH * TT * TT) / 256), 256>>>();
    tri_update<<<gNT, 256>>>();                    // A -= tril(QW) @ btil
    softmax_kernel<<<dim3(TT, NH), 256>>>();       // P in g_A (upper zeroed)

    // O = P @ V  (per head; output interleaved into [t, h*128+d])
    gemm_f32<<<dim3(HD / 64, TT / 64, NH), 256>>>(
        A, v, O, TT, TT, HD, DD,
        (long long)TT * TT, (long long)TT * HD, (long long)HD, 0);

    // out = O @ Wo
    gemm_f32<<<dim3(DD / 64, TT / 64, 1), 256>>>(O, Wo, out, DD, DD, DD, DD, 0, 0, 0, 0);
}

// round 5
// speedup vs baseline: 1.0589x; 1.0589x over previous
#include <cuda_runtime.h>
#include <cuda_bf16.h>
#include <math.h>

#define TT 2048
#define DD 1024
#define NH 8
#define HD 128
#define KC 4
#define CH 128
#define NCHUNK (TT / CH)
#define BM 128
#define BN 128
#define BKK 16
#define ATT_SCALE 0.08838834764831845f  // 1/sqrt(128)

// ---------------- scratch (device globals; no allocation allowed) ----------
__device__ float g_raw[4 * TT * DD];          // Qraw, Kraw, Vraw, Wpre
__device__ float g_q[NH * TT * HD];
__device__ float g_k[NH * TT * HD];
__device__ float g_v[NH * TT * HD];
__device__ float g_w[NH * TT * HD];
__device__ float g_beta[NH * TT];
__device__ float g_gpre[NH * TT];
__device__ float g_G[NH * TT];
__device__ float g_A[(size_t)NH * TT * TT];   // QK^T -> logits -> P
__device__ float g_QW[(size_t)NH * TT * TT];  // tril(q w^T, 0)
__device__ float g_Mw[(size_t)NH * TT * TT];  // strict-lower (w w^T)*beta_col
__device__ float g_bm[(size_t)NH * TT * TT];  // rhs -> bmat
__device__ float g_bt[(size_t)NH * TT * TT];  // btil = beta_row * bmat
__device__ float g_O[TT * DD];                // P@V in [t, h*128+d] layout

// ---------------- tf32 helpers ----------------------------------------------
__device__ __forceinline__ unsigned tf32_of(float x) {
    unsigned r;
    asm("cvt.rna.tf32.f32 %0, %1;" : "=r"(r) : "f"(x));
    return r;
}
__device__ __forceinline__ void split_tf32(float x, unsigned& h, unsigned& l) {
    h = tf32_of(x);
    l = tf32_of(x - __uint_as_float(h));
}
__device__ __forceinline__ void mma_tf32(float* c, const unsigned* a, unsigned b0, unsigned b1) {
    asm volatile(
        "mma.sync.aligned.m16n8k8.row.col.f32.tf32.tf32.f32 "
        "{%0,%1,%2,%3}, {%4,%5,%6,%7}, {%8,%9}, {%0,%1,%2,%3};"
        : "+f"(c[0]), "+f"(c[1]), "+f"(c[2]), "+f"(c[3])
        : "r"(a[0]), "r"(a[1]), "r"(a[2]), "r"(a[3]), "r"(b0), "r"(b1));
}

// ---------------- NN GEMM: C (=|-=) A[M,K] @ B[K,N], 3xTF32 ----------------
// flags: 1 = subtract-accumulate; 2 = triangular (kBeg=colBase, kEnd=rowBase+BM,
//        skip bx>by tiles); 4 = causal K limit (kEnd = min(K, rowBase+BM)).
__global__ __launch_bounds__(256) void mma_nn(
    const float* __restrict__ A, const float* __restrict__ B, float* __restrict__ C,
    int K, int lda, int ldb, int ldc,
    long long sA, long long sB, long long sC, int flags)
{
    const int bx = blockIdx.x, by = blockIdx.y;
    if ((flags & 2) && bx > by) return;
    A += (long long)blockIdx.z * sA;
    B += (long long)blockIdx.z * sB;
    C += (long long)blockIdx.z * sC;
    const int rowBase = by * BM, colBase = bx * BN;
    const int kBeg = (flags & 2) ? colBase : 0;
    const int kEnd = (flags & 6) ? min(K, rowBase + BM) : K;

    __shared__ unsigned AsH[BM][BKK + 4], AsL[BM][BKK + 4];   // stride 20
    __shared__ unsigned BsH[BKK][BN + 8], BsL[BKK][BN + 8];   // stride 136

    const int tid = threadIdx.x, lane = tid & 31, wid = tid >> 5;
    const int wr = wid & 3, wc = wid >> 2;
    const int g = lane >> 2, t4 = lane & 3;

    const int arow = tid >> 2, acol = (tid & 3) * 4;      // A: 64 rows x 16 cols / half
    const int bk = tid >> 5, bn = (tid & 31) * 4;         // B: 8 k-rows x 128 cols / half

    float acc[2][8][4] = {};
    float4 fa[2], fb[2];

    // prologue gmem load
    fa[0] = *(const float4*)(A + (long long)(rowBase + arow) * lda + kBeg + acol);
    fa[1] = *(const float4*)(A + (long long)(rowBase + 64 + arow) * lda + kBeg + acol);
    fb[0] = *(const float4*)(B + (long long)(kBeg + bk) * ldb + colBase + bn);
    fb[1] = *(const float4*)(B + (long long)(kBeg + 8 + bk) * ldb + colBase + bn);

    for (int kk = kBeg; kk < kEnd; kk += BKK) {
#pragma unroll
        for (int i = 0; i < 2; i++) {
            int r = i * 64 + arow;
            float va[4] = {fa[i].x, fa[i].y, fa[i].z, fa[i].w};
#pragma unroll
            for (int u = 0; u < 4; u++) split_tf32(va[u], AsH[r][acol + u], AsL[r][acol + u]);
            int kq = i * 8 + bk;
            float vb[4] = {fb[i].x, fb[i].y, fb[i].z, fb[i].w};
#pragma unroll
            for (int u = 0; u < 4; u++) split_tf32(vb[u], BsH[kq][bn + u], BsL[kq][bn + u]);
        }
        __syncthreads();
        const int nxt = kk + BKK;
        if (nxt < kEnd) {
            fa[0] = *(const float4*)(A + (long long)(rowBase + arow) * lda + nxt + acol);
            fa[1] = *(const float4*)(A + (long long)(rowBase + 64 + arow) * lda + nxt + acol);
            fb[0] = *(const float4*)(B + (long long)(nxt + bk) * ldb + colBase + bn);
            fb[1] = *(const float4*)(B + (long long)(nxt + 8 + bk) * ldb + colBase + bn);
        }
#pragma unroll
        for (int k8 = 0; k8 < BKK; k8 += 8) {
            unsigned aH[2][4], aL[2][4];
#pragma unroll
            for (int mt = 0; mt < 2; mt++) {
                int r = wr * 32 + mt * 16 + g, c = k8 + t4;
                aH[mt][0] = AsH[r][c];     aH[mt][1] = AsH[r + 8][c];
                aH[mt][2] = AsH[r][c + 4]; aH[mt][3] = AsH[r + 8][c + 4];
                aL[mt][0] = AsL[r][c];     aL[mt][1] = AsL[r + 8][c];
                aL[mt][2] = AsL[r][c + 4]; aL[mt][3] = AsL[r + 8][c + 4];
            }
#pragma unroll
            for (int nt = 0; nt < 8; nt++) {
                int n = wc * 64 + nt * 8 + g;
                unsigned bH0 = BsH[k8 + t4][n], bH1 = BsH[k8 + t4 + 4][n];
                unsigned bL0 = BsL[k8 + t4][n], bL1 = BsL[k8 + t4 + 4][n];
#pragma unroll
                for (int mt = 0; mt < 2; mt++) {
                    float* c = acc[mt][nt];
                    mma_tf32(c, aH[mt], bH0, bH1);
                    mma_tf32(c, aH[mt], bL0, bL1);
                    mma_tf32(c, aL[mt], bH0, bH1);
                }
            }
        }
        __syncthreads();
    }

#pragma unroll
    for (int mt = 0; mt < 2; mt++) {
#pragma unroll
        for (int nt = 0; nt < 8; nt++) {
            int r0 = rowBase + wr * 32 + mt * 16 + g;
            int c0 = colBase + wc * 64 + nt * 8 + t4 * 2;
            float* p0 = C + (long long)r0 * ldc + c0;
            float* p1 = C + (long long)(r0 + 8) * ldc + c0;
            if (flags & 1) {
                float2 v0 = *(float2*)p0;
                v0.x -= acc[mt][nt][0]; v0.y -= acc[mt][nt][1];
                *(float2*)p0 = v0;
                float2 v1 = *(float2*)p1;
                v1.x -= acc[mt][nt][2]; v1.y -= acc[mt][nt][3];
                *(float2*)p1 = v1;
            } else {
                float2 v0 = {acc[mt][nt][0], acc[mt][nt][1]};
                float2 v1 = {acc[mt][nt][2], acc[mt][nt][3]};
                *(float2*)p0 = v0;
                *(float2*)p1 = v1;
            }
        }
    }
}

// ---------------- NT GEMM: C = A @ B^T for [T,128] head operands, 3xTF32 ----
// modes: 0 = QK^T (skip upper tiles); 1 = tril(QW^T,0); 2 = strict lower,
// upper tiles zero-filled; 3 = strict-lower (WW^T)*beta[col].
__global__ __launch_bounds__(256) void mma_nt(
    const float* __restrict__ Aten, const float* __restrict__ Bten,
    float* __restrict__ C, const float* __restrict__ betaArr, int mode)
{
    const int bx = blockIdx.x, by = blockIdx.y, h = blockIdx.z;
    const int rowBase = by * BM, colBase = bx * BN;
    const int tid = threadIdx.x, lane = tid & 31, wid = tid >> 5;
    float* Ch = C + (size_t)h * TT * TT;
    if (bx > by) {
        if (mode == 2) {
            float4 z = {0.f, 0.f, 0.f, 0.f};
#pragma unroll
            for (int i = 0; i < 16; i++) {
                int fid = i * 256 + tid;
                int r = fid >> 5, c = (fid & 31) * 4;
                *(float4*)(Ch + (size_t)(rowBase + r) * TT + colBase + c) = z;
            }
        }
        return;
    }
    const float* A = Aten + (size_t)h * TT * HD;
    const float* B = Bten + (size_t)h * TT * HD;

    __shared__ unsigned AsH[BM][BKK + 4], AsL[BM][BKK + 4];   // stride 20
    __shared__ unsigned BsH[BN][BKK + 4], BsL[BN][BKK + 4];   // stride 20

    const int wr = wid & 3, wc = wid >> 2;
    const int g = lane >> 2, t4 = lane & 3;
    const int arow = tid >> 2, acol = (tid & 3) * 4;

    float acc[2][8][4] = {};
    float4 fa[2], fb[2];

    fa[0] = *(const float4*)(A + (size_t)(rowBase + arow) * HD + acol);
    fa[1] = *(const float4*)(A + (size_t)(rowBase + 64 + arow) * HD + acol);
    fb[0] = *(const float4*)(B + (size_t)(colBase + arow) * HD + acol);
    fb[1] = *(const float4*)(B + (size_t)(colBase + 64 + arow) * HD + acol);

    for (int kk = 0; kk < HD; kk += BKK) {
#pragma unroll
        for (int i = 0; i < 2; i++) {
            int r = i * 64 + arow;
            float va[4] = {fa[i].x, fa[i].y, fa[i].z, fa[i].w};
            float vb[4] = {fb[i].x, fb[i].y, fb[i].z, fb[i].w};
#pragma unroll
            for (int u = 0; u < 4; u++) {
                split_tf32(va[u], AsH[r][acol + u], AsL[r][acol + u]);
                split_tf32(vb[u], BsH[r][acol + u], BsL[r][acol + u]);
            }
        }
        __syncthreads();
        const int nxt = kk + BKK;
        if (nxt < HD) {
            fa[0] = *(const float4*)(A + (size_t)(rowBase + arow) * HD + nxt + acol);
            fa[1] = *(const float4*)(A + (size_t)(rowBase + 64 + arow) * HD + nxt + acol);
            fb[0] = *(const float4*)(B + (size_t)(colBase + arow) * HD + nxt + acol);
            fb[1] = *(const float4*)(B + (size_t)(colBase + 64 + arow) * HD + nxt + acol);
        }
#pragma unroll
        for (int k8 = 0; k8 < BKK; k8 += 8) {
            unsigned aH[2][4], aL[2][4];
#pragma unroll
            for (int mt = 0; mt < 2; mt++) {
                int r = wr * 32 + mt * 16 + g, c = k8 + t4;
                aH[mt][0] = AsH[r][c];     aH[mt][1] = AsH[r + 8][c];
                aH[mt][2] = AsH[r][c + 4]; aH[mt][3] = AsH[r + 8][c + 4];
                aL[mt][0] = AsL[r][c];     aL[mt][1] = AsL[r + 8][c];
                aL[mt][2] = AsL[r][c + 4]; aL[mt][3] = AsL[r + 8][c + 4];
            }
#pragma unroll
            for (int nt = 0; nt < 8; nt++) {
                int n = wc * 64 + nt * 8 + g;
                unsigned bH0 = BsH[n][k8 + t4], bH1 = BsH[n][k8 + t4 + 4];
                unsigned bL0 = BsL[n][k8 + t4], bL1 = BsL[n][k8 + t4 + 4];
#pragma unroll
                for (int mt = 0; mt < 2; mt++) {
                    float* c = acc[mt][nt];
                    mma_tf32(c, aH[mt], bH0, bH1);
                    mma_tf32(c, aH[mt], bL0, bL1);
                    mma_tf32(c, aL[mt], bH0, bH1);
                }
            }
        }
        __syncthreads();
    }

#pragma unroll
    for (int mt = 0; mt < 2; mt++) {
#pragma unroll
        for (int nt = 0; nt < 8; nt++) {
#pragma unroll
            for (int half = 0; half < 2; half++) {
                int t = rowBase + wr * 32 + mt * 16 + g + half * 8;
                int j = colBase + wc * 64 + nt * 8 + t4 * 2;
                float v0 = acc[mt][nt][half * 2 + 0];
                float v1 = acc[mt][nt][half * 2 + 1];
                if (mode == 1) {
                    v0 = (j <= t) ? v0 : 0.0f;
                    v1 = (j + 1 <= t) ? v1 : 0.0f;
                } else if (mode == 2) {
                    v0 = (j < t) ? v0 : 0.0f;
                    v1 = (j + 1 < t) ? v1 : 0.0f;
                } else if (mode == 3) {
                    v0 = (j < t) ? v0 * betaArr[h * TT + j] : 0.0f;
                    v1 = (j + 1 < t) ? v1 * betaArr[h * TT + j + 1] : 0.0f;
                }
                float2 out = {v0, v1};
                *(float2*)(Ch + (size_t)t * TT + j) = out;
            }
        }
    }
}

// ---------------- in-chunk forward substitution (warp per column) -----------
// Solves the unit-lower-triangular diagonal block; writes bm (unscaled) and
// btil = beta_row * bm.
__global__ __launch_bounds__(256) void chunk_solve(int chunk)
{
    const int h = blockIdx.y;
    const int tid = threadIdx.x, lane = tid & 31, wid = tid >> 5;
    const float* Mh = g_Mw + (size_t)h * TT * TT + (size_t)(chunk * CH) * TT + chunk * CH;
    float* bh = g_bm + (size_t)h * TT * TT + (size_t)(chunk * CH) * TT;
    float* bt = g_bt + (size_t)h * TT * TT + (size_t)(chunk * CH) * TT;
    const int j0 = blockIdx.x * 8;

    __shared__ float Mtri[CH * (CH - 1) / 2];   // strict lower, packed r*(r-1)/2 + s
    __shared__ float bs[CH][9];

    for (int r = wid + 1; r < CH; r += 8) {
        int base = r * (r - 1) / 2;
        for (int s = lane; s < r; s += 32) Mtri[base + s] = Mh[(size_t)r * TT + s];
    }
    {   // cooperative column-block load: 128 rows x 8 cols
        int r = tid >> 1, c = (tid & 1) * 4;
        float4 v = *(const float4*)(bh + (size_t)r * TT + j0 + c);
        bs[r][c + 0] = v.x; bs[r][c + 1] = v.y; bs[r][c + 2] = v.z; bs[r][c + 3] = v.w;
    }
    __syncthreads();

    // warp wid solves column j0+wid
    for (int r = 1; r < CH; r++) {
        int base = r * (r - 1) / 2;
        float sum = 0.0f;
        for (int s = lane; s < r; s += 32) sum += Mtri[base + s] * bs[s][wid];
#pragma unroll
        for (int o = 16; o > 0; o >>= 1) sum += __shfl_xor_sync(0xffffffffu, sum, o);
        if (lane == 0) bs[r][wid] -= sum;
        __syncwarp();
    }
    __syncthreads();

    {
        int r = tid >> 1, c = (tid & 1) * 4;
        float beta = g_beta[h * TT + chunk * CH + r];
        float4 v = {bs[r][c + 0], bs[r][c + 1], bs[r][c + 2], bs[r][c + 3]};
        *(float4*)(bh + (size_t)r * TT + j0 + c) = v;
        float4 vt = {v.x * beta, v.y * beta, v.z * beta, v.w * beta};
        *(float4*)(bt + (size_t)r * TT + j0 + c) = vt;
    }
}

// ---------------- prep: rms(q,k), v copy, conv+silu+l2norm w ----------------
__device__ __forceinline__ float block_reduce_128(float v, float* sh)
{
    int tid = threadIdx.x;
    sh[tid] = v; __syncthreads();
    for (int s = 64; s > 0; s >>= 1) {
        if (tid < s) sh[tid] += sh[tid + s];
        __syncthreads();
    }
    float r = sh[0]; __syncthreads();
    return r;
}

__global__ void prep_kernel(const float* __restrict__ qn_w,
                            const float* __restrict__ kn_w,
                            const float* __restrict__ convw)
{
    const int t = blockIdx.x, h = blockIdx.y, i = threadIdx.x;
    __shared__ float sh[128];
    const float* Qr = g_raw;
    const float* Kr = g_raw + (size_t)TT * DD;
    const float* Vr = g_raw + (size_t)2 * TT * DD;
    const float* Wp = g_raw + (size_t)3 * TT * DD;
    const int col = h * HD + i;
    const size_t out = ((size_t)h * TT + t) * HD + i;

    float qv = Qr[(size_t)t * DD + col];
    float s = block_reduce_128(qv * qv, sh);
    g_q[out] = qv * rsqrtf(s * (1.0f / HD) + 1e-6f) * qn_w[i];

    float kv = Kr[(size_t)t * DD + col];
    s = block_reduce_128(kv * kv, sh);
    g_k[out] = kv * rsqrtf(s * (1.0f / HD) + 1e-6f) * kn_w[i];

    g_v[out] = Vr[(size_t)t * DD + col];

    float wc = 0.0f;
#pragma unroll
    for (int tap = 0; tap < KC; tap++) {
        int tt = t - (KC - 1) + tap;
        if (tt >= 0) wc += Wp[(size_t)tt * DD + col] * convw[col * KC + tap];
    }
    wc = wc / (1.0f + __expf(-wc));         // silu
    s = block_reduce_128(wc * wc, sh);
    g_w[out] = wc * rsqrtf(s + 1e-6f);
}

// ---------------- beta = 2*sigmoid(x@Wbeta), gpre = x@Wg --------------------
__global__ void betag_kernel(const float* __restrict__ x,
                             const float* __restrict__ Wbeta,
                             const float* __restrict__ Wg)
{
    const int t = blockIdx.x;
    const int tid = threadIdx.x;
    const int wid = tid >> 5, lane = tid & 31;   // 8 warps = 8 heads
    const float* xr = x + (size_t)t * DD;
    float sb = 0.0f, sg = 0.0f;
    for (int dd = lane; dd < DD; dd += 32) {
        float xv = xr[dd];
        sb += xv * Wbeta[dd * NH + wid];
        sg += xv * Wg[dd * NH + wid];
    }
#pragma unroll
    for (int o = 16; o > 0; o >>= 1) {
        sb += __shfl_down_sync(0xffffffffu, sb, o);
        sg += __shfl_down_sync(0xffffffffu, sg, o);
    }
    if (lane == 0) {
        g_beta[wid * TT + t] = 2.0f / (1.0f + __expf(-sb));
        g_gpre[wid * TT + t] = sg;
    }
}

// ---------------- G = cumsum(log_sigmoid(gpre)) over t ----------------------
__global__ void cumsum_kernel()
{
    int h = threadIdx.x;
    if (h >= NH) return;
    float run = 0.0f;
    for (int t = 0; t < TT; t++) {
        float x = g_gpre[h * TT + t];
        float ls = fminf(x, 0.0f) - log1pf(__expf(-fabsf(x)));
        run += ls;
        g_G[h * TT + t] = run;
    }
}

// ---------------- masked softmax with FoX gates; zero the upper triangle ----
__global__ void softmax_kernel()
{
    const int t = blockIdx.x, h = blockIdx.y;
    float* row = g_A + ((size_t)h * TT + t) * TT;
    const float* Gh = g_G + h * TT;
    const float Gt = Gh[t];
    const int n = t + 1;
    const int tid = threadIdx.x;
    __shared__ float red[256];

    float m = -1e30f;
    for (int j = tid; j < n; j += 256) {
        float l = row[j] * ATT_SCALE + Gt - Gh[j];
        m = fmaxf(m, l);
    }
    red[tid] = m; __syncthreads();
    for (int s = 128; s > 0; s >>= 1) {
        if (tid < s) red[tid] = fmaxf(red[tid], red[tid + s]);
        __syncthreads();
    }
    m = red[0]; __syncthreads();

    float sum = 0.0f;
    for (int j = tid; j < n; j += 256) {
        float l = row[j] * ATT_SCALE + Gt - Gh[j];
        sum += __expf(l - m);
    }
    red[tid] = sum; __syncthreads();
    for (int s = 128; s > 0; s >>= 1) {
        if (tid < s) red[tid] += red[tid + s];
        __syncthreads();
    }
    const float inv = 1.0f / red[0];

    for (int j = tid; j < n; j += 256) {
        float l = row[j] * ATT_SCALE + Gt - Gh[j];
        row[j] = __expf(l - m) * inv;
    }
    for (int j = n + tid; j < TT; j += 256) row[j] = 0.0f;
}

// ---------------------------------------------------------------------------
extern "C" void kernel_launch(void* const* d_in, const int* in_sizes, int n_in,
                              void* d_out, int out_size)
{
    const float* x     = (const float*)d_in[0];
    const float* Wq    = (const float*)d_in[1];
    const float* Wk    = (const float*)d_in[2];
    const float* Wv    = (const float*)d_in[3];
    const float* Ww    = (const float*)d_in[4];
    const float* Wbeta = (const float*)d_in[5];
    const float* Wg    = (const float*)d_in[6];
    const float* Wo    = (const float*)d_in[7];
    const float* convw = (const float*)d_in[8];
    const float* qnw   = (const float*)d_in[9];
    const float* knw   = (const float*)d_in[10];
    float* out = (float*)d_out;

    float *raw, *q, *k, *v, *w, *A, *QW, *Mw, *bm, *bt, *O, *beta;
    cudaGetSymbolAddress((void**)&raw, g_raw);
    cudaGetSymbolAddress((void**)&q, g_q);
    cudaGetSymbolAddress((void**)&k, g_k);
    cudaGetSymbolAddress((void**)&v, g_v);
    cudaGetSymbolAddress((void**)&w, g_w);
    cudaGetSymbolAddress((void**)&A, g_A);
    cudaGetSymbolAddress((void**)&QW, g_QW);
    cudaGetSymbolAddress((void**)&Mw, g_Mw);
    cudaGetSymbolAddress((void**)&bm, g_bm);
    cudaGetSymbolAddress((void**)&bt, g_bt);
    cudaGetSymbolAddress((void**)&O, g_O);
    cudaGetSymbolAddress((void**)&beta, g_beta);

    const long long TTTT = (long long)TT * TT;

    // Q, K, V, Wpre projections (2048x1024x1024 each)
    const dim3 gProj(DD / BN, TT / BM, 1);
    mma_nn<<<gProj, 256>>>(x, Wq, raw + (size_t)0 * TT * DD, DD, DD, DD, DD, 0, 0, 0, 0);
    mma_nn<<<gProj, 256>>>(x, Wk, raw + (size_t)1 * TT * DD, DD, DD, DD, DD, 0, 0, 0, 0);
    mma_nn<<<gProj, 256>>>(x, Wv, raw + (size_t)2 * TT * DD, DD, DD, DD, DD, 0, 0, 0, 0);
    mma_nn<<<gProj, 256>>>(x, Ww, raw + (size_t)3 * TT * DD, DD, DD, DD, DD, 0, 0, 0, 0);

    betag_kernel<<<TT, 256>>>(x, Wbeta, Wg);
    cumsum_kernel<<<1, 32>>>();
    prep_kernel<<<dim3(TT, NH), 128>>>(qnw, knw, convw);

    const dim3 gNT(TT / BN, TT / BM, NH);
    mma_nt<<<gNT, 256>>>(q, k, A, nullptr, 0);    // QK^T (lower tiles)
    mma_nt<<<gNT, 256>>>(q, w, QW, nullptr, 1);   // tril(QW^T, 0)
    mma_nt<<<gNT, 256>>>(w, k, bm, nullptr, 2);   // rhs = tril(WK^T,-1), upper zeroed
    mma_nt<<<gNT, 256>>>(w, w, Mw, beta, 3);      // strict-lower (WW^T)*beta_col  [FIXED: device ptr]

    // blocked forward substitution: M bmat = rhs  (16 stages of 128)
    chunk_solve<<<dim3(16, NH), 256>>>(0);
    for (int c = 1; c < NCHUNK; c++) {
        mma_nn<<<dim3(c, 1, NH), 256>>>(
            Mw + (size_t)c * CH * TT, bm, bm + (size_t)c * CH * TT,
            c * CH, TT, TT, TT, TTTT, TTTT, TTTT, 1);
        chunk_solve<<<dim3((c + 1) * 16, NH), 256>>>(c);
    }

    // A -= tril(QW) @ btil   (triangular k-range, subtract)
    mma_nn<<<gNT, 256>>>(QW, bt, A, TT, TT, TT, TT, TTTT, TTTT, TTTT, 3);

    softmax_kernel<<<dim3(TT, NH), 256>>>();       // P in g_A (upper zeroed)

    // O = P @ V  (causal k-range)
    mma_nn<<<dim3(1, TT / BM, NH), 256>>>(
        A, v, O, TT, TT, HD, DD, TTTT, (long long)TT * HD, HD, 4);

    // out = O @ Wo
    mma_nn<<<dim3(DD / BN, TT / BM, 1), 256>>>(O, Wo, out, DD, DD, DD, DD, 0, 0, 0, 0);
}

// round 6
// speedup vs baseline: 1.3863x; 1.3092x over previous
#include <cuda_runtime.h>
#include <cuda_bf16.h>
#include <math.h>

#define TT 2048
#define DD 1024
#define NH 8
#define HD 128
#define KC 4
#define CH 128
#define NCHUNK (TT / CH)
#define BM 128
#define BN 128
#define BKK 16
#define ATT_SCALE 0.08838834764831845f  // 1/sqrt(128)

// dynamic smem: per-stage word counts
#define NN_STAGE 9472    // AsH 2560 | AsL 2560 | BsH 2176 | BsL 2176
#define NT_STAGE 10240   // AsH 2560 | AsL 2560 | BsH 2560 | BsL 2560
#define SMNN (2 * NN_STAGE * 4)
#define SMNT (2 * NT_STAGE * 4)

// ---------------- scratch (device globals; no allocation allowed) ----------
__device__ float g_raw[4 * TT * DD];          // Qraw,Kraw,Vraw,Wpre; later PV partials
__device__ float g_q[NH * TT * HD];
__device__ float g_k[NH * TT * HD];
__device__ float g_v[NH * TT * HD];
__device__ float g_w[NH * TT * HD];
__device__ float g_beta[NH * TT];
__device__ float g_gpre[NH * TT];
__device__ float g_G[NH * TT];
__device__ float g_A[(size_t)NH * TT * TT];   // QK^T -> logits -> P
__device__ float g_QW[(size_t)NH * TT * TT];  // tril(q w^T, 0)
__device__ float g_Mw[(size_t)NH * TT * TT];  // strict-lower (w w^T)*beta_col
__device__ float g_bm[(size_t)NH * TT * TT];  // rhs -> bmat
__device__ float g_bt[(size_t)NH * TT * TT];  // btil = beta_row * bmat
__device__ float g_O[TT * DD];                // P@V in [t, h*128+d] layout

// ---------------- tf32 helpers ----------------------------------------------
__device__ __forceinline__ unsigned tf32_of(float x) {
    unsigned r;
    asm("cvt.rna.tf32.f32 %0, %1;" : "=r"(r) : "f"(x));
    return r;
}
__device__ __forceinline__ void split_tf32(float x, unsigned& h, unsigned& l) {
    h = tf32_of(x);
    l = tf32_of(x - __uint_as_float(h));
}
__device__ __forceinline__ void mma_tf32(float* c, const unsigned* a, unsigned b0, unsigned b1) {
    asm volatile(
        "mma.sync.aligned.m16n8k8.row.col.f32.tf32.tf32.f32 "
        "{%0,%1,%2,%3}, {%4,%5,%6,%7}, {%8,%9}, {%0,%1,%2,%3};"
        : "+f"(c[0]), "+f"(c[1]), "+f"(c[2]), "+f"(c[3])
        : "r"(a[0]), "r"(a[1]), "r"(a[2]), "r"(a[3]), "r"(b0), "r"(b1));
}

// ---------------- NN GEMM: C (=|-=) A[M,K] @ B[K,N], 3xTF32, 2-stage --------
// flags: 1 = subtract-accumulate; 2 = triangular (kBeg=colBase, kEnd=rowBase+BM,
//        skip bx>by tiles); 4 = causal K limit; 8 = split-K PV mode
//        (z = head + 8*split, kRange [split*512, split*512+512) ∩ causal,
//         C = base + split*TT*DD + head*sC).
__global__ __launch_bounds__(256) void mma_nn(
    const float* __restrict__ A, const float* __restrict__ B, float* __restrict__ C,
    int K, int lda, int ldb, int ldc,
    long long sA, long long sB, long long sC, int flags)
{
    const int bx = blockIdx.x, by = blockIdx.y;
    if ((flags & 2) && bx > by) return;
    const int rowBase = by * BM, colBase = bx * BN;
    int kBeg, kEnd;
    if (flags & 8) {
        int h = blockIdx.z & 7, sp = blockIdx.z >> 3;
        A += (long long)h * sA;
        B += (long long)h * sB;
        C += (size_t)sp * TT * DD + (long long)h * sC;
        kBeg = sp * 512;
        kEnd = min(min(K, rowBase + BM), kBeg + 512);
    } else {
        A += (long long)blockIdx.z * sA;
        B += (long long)blockIdx.z * sB;
        C += (long long)blockIdx.z * sC;
        kBeg = (flags & 2) ? colBase : 0;
        kEnd = (flags & 6) ? min(K, rowBase + BM) : K;
    }
    const int nT = (kEnd > kBeg) ? (kEnd - kBeg) / BKK : 0;

    extern __shared__ unsigned sm[];

    const int tid = threadIdx.x, lane = tid & 31, wid = tid >> 5;
    const int wr = wid & 3, wc = wid >> 2;
    const int g = lane >> 2, t4 = lane & 3;
    const int arow = tid >> 2, acol = (tid & 3) * 4;
    const int bk = tid >> 5, bn = (tid & 31) * 4;

    float acc[2][8][4] = {};
    float4 fa[2], fb[2];

    auto ldgT = [&](int kk) {
        fa[0] = *(const float4*)(A + (long long)(rowBase + arow) * lda + kk + acol);
        fa[1] = *(const float4*)(A + (long long)(rowBase + 64 + arow) * lda + kk + acol);
        fb[0] = *(const float4*)(B + (long long)(kk + bk) * ldb + colBase + bn);
        fb[1] = *(const float4*)(B + (long long)(kk + 8 + bk) * ldb + colBase + bn);
    };
    auto stsT = [&](int st) {
        unsigned* AH = sm + st * NN_STAGE;
        unsigned* AL = AH + 2560;
        unsigned* BH = AH + 5120;
        unsigned* BL = AH + 7296;
#pragma unroll
        for (int i = 0; i < 2; i++) {
            int r = i * 64 + arow;
            float va[4] = {fa[i].x, fa[i].y, fa[i].z, fa[i].w};
#pragma unroll
            for (int u = 0; u < 4; u++) split_tf32(va[u], AH[r * 20 + acol + u], AL[r * 20 + acol + u]);
            int kq = i * 8 + bk;
            float vb[4] = {fb[i].x, fb[i].y, fb[i].z, fb[i].w};
#pragma unroll
            for (int u = 0; u < 4; u++) split_tf32(vb[u], BH[kq * 136 + bn + u], BL[kq * 136 + bn + u]);
        }
    };

    if (nT > 0) {
        ldgT(kBeg);
        stsT(0);
        if (nT > 1) ldgT(kBeg + BKK);
        __syncthreads();
    }

    for (int i = 0; i < nT; i++) {
        if (i + 1 < nT) stsT((i + 1) & 1);
        if (i + 2 < nT) ldgT(kBeg + (i + 2) * BKK);
        const unsigned* AH = sm + (i & 1) * NN_STAGE;
        const unsigned* AL = AH + 2560;
        const unsigned* BH = AH + 5120;
        const unsigned* BL = AH + 7296;
#pragma unroll
        for (int k8 = 0; k8 < BKK; k8 += 8) {
            unsigned aH[2][4], aL[2][4];
#pragma unroll
            for (int mt = 0; mt < 2; mt++) {
                int r = wr * 32 + mt * 16 + g, c = k8 + t4;
                aH[mt][0] = AH[r * 20 + c];       aH[mt][1] = AH[(r + 8) * 20 + c];
                aH[mt][2] = AH[r * 20 + c + 4];   aH[mt][3] = AH[(r + 8) * 20 + c + 4];
                aL[mt][0] = AL[r * 20 + c];       aL[mt][1] = AL[(r + 8) * 20 + c];
                aL[mt][2] = AL[r * 20 + c + 4];   aL[mt][3] = AL[(r + 8) * 20 + c + 4];
            }
#pragma unroll
            for (int nt = 0; nt < 8; nt++) {
                int n = wc * 64 + nt * 8 + g;
                unsigned bH0 = BH[(k8 + t4) * 136 + n], bH1 = BH[(k8 + t4 + 4) * 136 + n];
                unsigned bL0 = BL[(k8 + t4) * 136 + n], bL1 = BL[(k8 + t4 + 4) * 136 + n];
#pragma unroll
                for (int mt = 0; mt < 2; mt++) {
                    float* c = acc[mt][nt];
                    mma_tf32(c, aH[mt], bH0, bH1);
                    mma_tf32(c, aH[mt], bL0, bL1);
                    mma_tf32(c, aL[mt], bH0, bH1);
                }
            }
        }
        __syncthreads();
    }

#pragma unroll
    for (int mt = 0; mt < 2; mt++) {
#pragma unroll
        for (int nt = 0; nt < 8; nt++) {
            int r0 = rowBase + wr * 32 + mt * 16 + g;
            int c0 = colBase + wc * 64 + nt * 8 + t4 * 2;
            float* p0 = C + (long long)r0 * ldc + c0;
            float* p1 = C + (long long)(r0 + 8) * ldc + c0;
            if (flags & 1) {
                float2 v0 = *(float2*)p0;
                v0.x -= acc[mt][nt][0]; v0.y -= acc[mt][nt][1];
                *(float2*)p0 = v0;
                float2 v1 = *(float2*)p1;
                v1.x -= acc[mt][nt][2]; v1.y -= acc[mt][nt][3];
                *(float2*)p1 = v1;
            } else {
                float2 v0 = {acc[mt][nt][0], acc[mt][nt][1]};
                float2 v1 = {acc[mt][nt][2], acc[mt][nt][3]};
                *(float2*)p0 = v0;
                *(float2*)p1 = v1;
            }
        }
    }
}

// ---------------- NT GEMM: C = A @ B^T for [T,128] head operands, 2-stage ---
// modes: 0 = QK^T (skip upper tiles); 1 = tril(QW^T,0); 2 = strict lower,
// upper tiles zero-filled; 3 = strict-lower (WW^T)*beta[col].
__global__ __launch_bounds__(256) void mma_nt(
    const float* __restrict__ Aten, const float* __restrict__ Bten,
    float* __restrict__ C, const float* __restrict__ betaArr, int mode)
{
    const int bx = blockIdx.x, by = blockIdx.y, h = blockIdx.z;
    const int rowBase = by * BM, colBase = bx * BN;
    const int tid = threadIdx.x, lane = tid & 31, wid = tid >> 5;
    float* Ch = C + (size_t)h * TT * TT;
    if (bx > by) {
        if (mode == 2) {
            float4 z = {0.f, 0.f, 0.f, 0.f};
#pragma unroll
            for (int i = 0; i < 16; i++) {
                int fid = i * 256 + tid;
                int r = fid >> 5, c = (fid & 31) * 4;
                *(float4*)(Ch + (size_t)(rowBase + r) * TT + colBase + c) = z;
            }
        }
        return;
    }
    const float* A = Aten + (size_t)h * TT * HD;
    const float* B = Bten + (size_t)h * TT * HD;

    extern __shared__ unsigned sm[];

    const int wr = wid & 3, wc = wid >> 2;
    const int g = lane >> 2, t4 = lane & 3;
    const int arow = tid >> 2, acol = (tid & 3) * 4;

    float acc[2][8][4] = {};
    float4 fa[2], fb[2];

    auto ldgT = [&](int kk) {
        fa[0] = *(const float4*)(A + (size_t)(rowBase + arow) * HD + kk + acol);
        fa[1] = *(const float4*)(A + (size_t)(rowBase + 64 + arow) * HD + kk + acol);
        fb[0] = *(const float4*)(B + (size_t)(colBase + arow) * HD + kk + acol);
        fb[1] = *(const float4*)(B + (size_t)(colBase + 64 + arow) * HD + kk + acol);
    };
    auto stsT = [&](int st) {
        unsigned* AH = sm + st * NT_STAGE;
        unsigned* AL = AH + 2560;
        unsigned* BH = AH + 5120;
        unsigned* BL = AH + 7680;
#pragma unroll
        for (int i = 0; i < 2; i++) {
            int r = i * 64 + arow;
            float va[4] = {fa[i].x, fa[i].y, fa[i].z, fa[i].w};
            float vb[4] = {fb[i].x, fb[i].y, fb[i].z, fb[i].w};
#pragma unroll
            for (int u = 0; u < 4; u++) {
                split_tf32(va[u], AH[r * 20 + acol + u], AL[r * 20 + acol + u]);
                split_tf32(vb[u], BH[r * 20 + acol + u], BL[r * 20 + acol + u]);
            }
        }
    };

    const int nT = HD / BKK;   // 8
    ldgT(0);
    stsT(0);
    ldgT(BKK);
    __syncthreads();

    for (int i = 0; i < nT; i++) {
        if (i + 1 < nT) stsT((i + 1) & 1);
        if (i + 2 < nT) ldgT((i + 2) * BKK);
        const unsigned* AH = sm + (i & 1) * NT_STAGE;
        const unsigned* AL = AH + 2560;
        const unsigned* BH = AH + 5120;
        const unsigned* BL = AH + 7680;
#pragma unroll
        for (int k8 = 0; k8 < BKK; k8 += 8) {
            unsigned aH[2][4], aL[2][4];
#pragma unroll
            for (int mt = 0; mt < 2; mt++) {
                int r = wr * 32 + mt * 16 + g, c = k8 + t4;
                aH[mt][0] = AH[r * 20 + c];       aH[mt][1] = AH[(r + 8) * 20 + c];
                aH[mt][2] = AH[r * 20 + c + 4];   aH[mt][3] = AH[(r + 8) * 20 + c + 4];
                aL[mt][0] = AL[r * 20 + c];       aL[mt][1] = AL[(r + 8) * 20 + c];
                aL[mt][2] = AL[r * 20 + c + 4];   aL[mt][3] = AL[(r + 8) * 20 + c + 4];
            }
#pragma unroll
            for (int nt = 0; nt < 8; nt++) {
                int n = wc * 64 + nt * 8 + g;
                unsigned bH0 = BH[n * 20 + k8 + t4], bH1 = BH[n * 20 + k8 + t4 + 4];
                unsigned bL0 = BL[n * 20 + k8 + t4], bL1 = BL[n * 20 + k8 + t4 + 4];
#pragma unroll
                for (int mt = 0; mt < 2; mt++) {
                    float* c = acc[mt][nt];
                    mma_tf32(c, aH[mt], bH0, bH1);
                    mma_tf32(c, aH[mt], bL0, bL1);
                    mma_tf32(c, aL[mt], bH0, bH1);
                }
            }
        }
        __syncthreads();
    }

#pragma unroll
    for (int mt = 0; mt < 2; mt++) {
#pragma unroll
        for (int nt = 0; nt < 8; nt++) {
#pragma unroll
            for (int half = 0; half < 2; half++) {
                int t = rowBase + wr * 32 + mt * 16 + g + half * 8;
                int j = colBase + wc * 64 + nt * 8 + t4 * 2;
                float v0 = acc[mt][nt][half * 2 + 0];
                float v1 = acc[mt][nt][half * 2 + 1];
                if (mode == 1) {
                    v0 = (j <= t) ? v0 : 0.0f;
                    v1 = (j + 1 <= t) ? v1 : 0.0f;
                } else if (mode == 2) {
                    v0 = (j < t) ? v0 : 0.0f;
                    v1 = (j + 1 < t) ? v1 : 0.0f;
                } else if (mode == 3) {
                    v0 = (j < t) ? v0 * betaArr[h * TT + j] : 0.0f;
                    v1 = (j + 1 < t) ? v1 * betaArr[h * TT + j + 1] : 0.0f;
                }
                float2 out = {v0, v1};
                *(float2*)(Ch + (size_t)t * TT + j) = out;
            }
        }
    }
}

// ---------------- in-chunk forward substitution (warp per column) -----------
__global__ __launch_bounds__(256) void chunk_solve(int chunk)
{
    const int h = blockIdx.y;
    const int tid = threadIdx.x, lane = tid & 31, wid = tid >> 5;
    const float* Mh = g_Mw + (size_t)h * TT * TT + (size_t)(chunk * CH) * TT + chunk * CH;
    float* bh = g_bm + (size_t)h * TT * TT + (size_t)(chunk * CH) * TT;
    float* bt = g_bt + (size_t)h * TT * TT + (size_t)(chunk * CH) * TT;
    const int j0 = blockIdx.x * 8;

    __shared__ float Mtri[CH * (CH - 1) / 2];   // strict lower, packed r*(r-1)/2 + s
    __shared__ float bs[CH][9];

    for (int r = wid + 1; r < CH; r += 8) {
        int base = r * (r - 1) / 2;
        for (int s = lane; s < r; s += 32) Mtri[base + s] = Mh[(size_t)r * TT + s];
    }
    {   // cooperative column-block load: 128 rows x 8 cols
        int r = tid >> 1, c = (tid & 1) * 4;
        float4 v = *(const float4*)(bh + (size_t)r * TT + j0 + c);
        bs[r][c + 0] = v.x; bs[r][c + 1] = v.y; bs[r][c + 2] = v.z; bs[r][c + 3] = v.w;
    }
    __syncthreads();

    // warp wid solves column j0+wid
    for (int r = 1; r < CH; r++) {
        int base = r * (r - 1) / 2;
        float sum = 0.0f;
        for (int s = lane; s < r; s += 32) sum += Mtri[base + s] * bs[s][wid];
#pragma unroll
        for (int o = 16; o > 0; o >>= 1) sum += __shfl_xor_sync(0xffffffffu, sum, o);
        if (lane == 0) bs[r][wid] -= sum;
        __syncwarp();
    }
    __syncthreads();

    {
        int r = tid >> 1, c = (tid & 1) * 4;
        float beta = g_beta[h * TT + chunk * CH + r];
        float4 v = {bs[r][c + 0], bs[r][c + 1], bs[r][c + 2], bs[r][c + 3]};
        *(float4*)(bh + (size_t)r * TT + j0 + c) = v;
        float4 vt = {v.x * beta, v.y * beta, v.z * beta, v.w * beta};
        *(float4*)(bt + (size_t)r * TT + j0 + c) = vt;
    }
}

// ---------------- reduce 4 split-K partials (in g_raw) into g_O --------------
__global__ void reduce_pv()
{
    size_t i = ((size_t)blockIdx.x * 256 + threadIdx.x) * 4;
    float4 a = *(const float4*)(g_raw + i);
    float4 b = *(const float4*)(g_raw + i + (size_t)TT * DD);
    float4 c = *(const float4*)(g_raw + i + (size_t)2 * TT * DD);
    float4 d = *(const float4*)(g_raw + i + (size_t)3 * TT * DD);
    float4 o = {a.x + b.x + c.x + d.x, a.y + b.y + c.y + d.y,
                a.z + b.z + c.z + d.z, a.w + b.w + c.w + d.w};
    *(float4*)(g_O + i) = o;
}

// ---------------- prep: rms(q,k), v copy, conv+silu+l2norm w ----------------
__device__ __forceinline__ float block_reduce_128(float v, float* sh)
{
    int tid = threadIdx.x;
    sh[tid] = v; __syncthreads();
    for (int s = 64; s > 0; s >>= 1) {
        if (tid < s) sh[tid] += sh[tid + s];
        __syncthreads();
    }
    float r = sh[0]; __syncthreads();
    return r;
}

__global__ void prep_kernel(const float* __restrict__ qn_w,
                            const float* __restrict__ kn_w,
                            const float* __restrict__ convw)
{
    const int t = blockIdx.x, h = blockIdx.y, i = threadIdx.x;
    __shared__ float sh[128];
    const float* Qr = g_raw;
    const float* Kr = g_raw + (size_t)TT * DD;
    const float* Vr = g_raw + (size_t)2 * TT * DD;
    const float* Wp = g_raw + (size_t)3 * TT * DD;
    const int col = h * HD + i;
    const size_t out = ((size_t)h * TT + t) * HD + i;

    float qv = Qr[(size_t)t * DD + col];
    float s = block_reduce_128(qv * qv, sh);
    g_q[out] = qv * rsqrtf(s * (1.0f / HD) + 1e-6f) * qn_w[i];

    float kv = Kr[(size_t)t * DD + col];
    s = block_reduce_128(kv * kv, sh);
    g_k[out] = kv * rsqrtf(s * (1.0f / HD) + 1e-6f) * kn_w[i];

    g_v[out] = Vr[(size_t)t * DD + col];

    float wc = 0.0f;
#pragma unroll
    for (int tap = 0; tap < KC; tap++) {
        int tt = t - (KC - 1) + tap;
        if (tt >= 0) wc += Wp[(size_t)tt * DD + col] * convw[col * KC + tap];
    }
    wc = wc / (1.0f + __expf(-wc));         // silu
    s = block_reduce_128(wc * wc, sh);
    g_w[out] = wc * rsqrtf(s + 1e-6f);
}

// ---------------- beta = 2*sigmoid(x@Wbeta), gpre = x@Wg --------------------
__global__ void betag_kernel(const float* __restrict__ x,
                             const float* __restrict__ Wbeta,
                             const float* __restrict__ Wg)
{
    const int t = blockIdx.x;
    const int tid = threadIdx.x;
    const int wid = tid >> 5, lane = tid & 31;   // 8 warps = 8 heads
    const float* xr = x + (size_t)t * DD;
    float sb = 0.0f, sg = 0.0f;
    for (int dd = lane; dd < DD; dd += 32) {
        float xv = xr[dd];
        sb += xv * Wbeta[dd * NH + wid];
        sg += xv * Wg[dd * NH + wid];
    }
#pragma unroll
    for (int o = 16; o > 0; o >>= 1) {
        sb += __shfl_down_sync(0xffffffffu, sb, o);
        sg += __shfl_down_sync(0xffffffffu, sg, o);
    }
    if (lane == 0) {
        g_beta[wid * TT + t] = 2.0f / (1.0f + __expf(-sb));
        g_gpre[wid * TT + t] = sg;
    }
}

// ---------------- G = cumsum(log_sigmoid(gpre)); warp-scan per head ---------
__global__ void cumsum_kernel()
{
    const int wid = threadIdx.x >> 5;       // head
    const int lane = threadIdx.x & 31;
    float carry = 0.0f;
    for (int base = 0; base < TT; base += 32) {
        float x = g_gpre[wid * TT + base + lane];
        float ls = fminf(x, 0.0f) - log1pf(__expf(-fabsf(x)));
#pragma unroll
        for (int o = 1; o < 32; o <<= 1) {
            float t = __shfl_up_sync(0xffffffffu, ls, o);
            if (lane >= o) ls += t;
        }
        ls += carry;
        g_G[wid * TT + base + lane] = ls;
        carry = __shfl_sync(0xffffffffu, ls, 31);
    }
}

// ---------------- masked softmax with FoX gates; zero the upper triangle ----
__global__ void softmax_kernel()
{
    const int t = blockIdx.x, h = blockIdx.y;
    float* row = g_A + ((size_t)h * TT + t) * TT;
    const float* Gh = g_G + h * TT;
    const float Gt = Gh[t];
    const int n = t + 1;
    const int tid = threadIdx.x;
    __shared__ float red[256];

    float m = -1e30f;
    for (int j = tid; j < n; j += 256) {
        float l = row[j] * ATT_SCALE + Gt - Gh[j];
        m = fmaxf(m, l);
    }
    red[tid] = m; __syncthreads();
    for (int s = 128; s > 0; s >>= 1) {
        if (tid < s) red[tid] = fmaxf(red[tid], red[tid + s]);
        __syncthreads();
    }
    m = red[0]; __syncthreads();

    float sum = 0.0f;
    for (int j = tid; j < n; j += 256) {
        float l = row[j] * ATT_SCALE + Gt - Gh[j];
        sum += __expf(l - m);
    }
    red[tid] = sum; __syncthreads();
    for (int s = 128; s > 0; s >>= 1) {
        if (tid < s) red[tid] += red[tid + s];
        __syncthreads();
    }
    const float inv = 1.0f / red[0];

    for (int j = tid; j < n; j += 256) {
        float l = row[j] * ATT_SCALE + Gt - Gh[j];
        row[j] = __expf(l - m) * inv;
    }
    for (int j = n + tid; j < TT; j += 256) row[j] = 0.0f;
}

// ---------------------------------------------------------------------------
extern "C" void kernel_launch(void* const* d_in, const int* in_sizes, int n_in,
                              void* d_out, int out_size)
{
    const float* x     = (const float*)d_in[0];
    const float* Wq    = (const float*)d_in[1];
    const float* Wk    = (const float*)d_in[2];
    const float* Wv    = (const float*)d_in[3];
    const float* Ww    = (const float*)d_in[4];
    const float* Wbeta = (const float*)d_in[5];
    const float* Wg    = (const float*)d_in[6];
    const float* Wo    = (const float*)d_in[7];
    const float* convw = (const float*)d_in[8];
    const float* qnw   = (const float*)d_in[9];
    const float* knw   = (const float*)d_in[10];
    float* out = (float*)d_out;

    cudaFuncSetAttribute(mma_nn, cudaFuncAttributeMaxDynamicSharedMemorySize, SMNN);
    cudaFuncSetAttribute(mma_nt, cudaFuncAttributeMaxDynamicSharedMemorySize, SMNT);

    float *raw, *q, *k, *v, *w, *A, *QW, *Mw, *bm, *bt, *O, *beta;
    cudaGetSymbolAddress((void**)&raw, g_raw);
    cudaGetSymbolAddress((void**)&q, g_q);
    cudaGetSymbolAddress((void**)&k, g_k);
    cudaGetSymbolAddress((void**)&v, g_v);
    cudaGetSymbolAddress((void**)&w, g_w);
    cudaGetSymbolAddress((void**)&A, g_A);
    cudaGetSymbolAddress((void**)&QW, g_QW);
    cudaGetSymbolAddress((void**)&Mw, g_Mw);
    cudaGetSymbolAddress((void**)&bm, g_bm);
    cudaGetSymbolAddress((void**)&bt, g_bt);
    cudaGetSymbolAddress((void**)&O, g_O);
    cudaGetSymbolAddress((void**)&beta, g_beta);

    const long long TTTT = (long long)TT * TT;

    // Q, K, V, Wpre projections (2048x1024x1024 each)
    const dim3 gProj(DD / BN, TT / BM, 1);
    mma_nn<<<gProj, 256, SMNN>>>(x, Wq, raw + (size_t)0 * TT * DD, DD, DD, DD, DD, 0, 0, 0, 0);
    mma_nn<<<gProj, 256, SMNN>>>(x, Wk, raw + (size_t)1 * TT * DD, DD, DD, DD, DD, 0, 0, 0, 0);
    mma_nn<<<gProj, 256, SMNN>>>(x, Wv, raw + (size_t)2 * TT * DD, DD, DD, DD, DD, 0, 0, 0, 0);
    mma_nn<<<gProj, 256, SMNN>>>(x, Ww, raw + (size_t)3 * TT * DD, DD, DD, DD, DD, 0, 0, 0, 0);

    betag_kernel<<<TT, 256>>>(x, Wbeta, Wg);
    cumsum_kernel<<<1, 256>>>();
    prep_kernel<<<dim3(TT, NH), 128>>>(qnw, knw, convw);

    const dim3 gNT(TT / BN, TT / BM, NH);
    mma_nt<<<gNT, 256, SMNT>>>(q, k, A, nullptr, 0);    // QK^T (lower tiles)
    mma_nt<<<gNT, 256, SMNT>>>(q, w, QW, nullptr, 1);   // tril(QW^T, 0)
    mma_nt<<<gNT, 256, SMNT>>>(w, k, bm, nullptr, 2);   // rhs = tril(WK^T,-1)
    mma_nt<<<gNT, 256, SMNT>>>(w, w, Mw, beta, 3);      // strict-lower (WW^T)*beta_col

    // right-looking blocked forward substitution: M bmat = rhs
    chunk_solve<<<dim3(16, NH), 256>>>(0);
    for (int c = 0; c < NCHUNK - 1; c++) {
        // trailing update: bm[rows > (c+1)CH, cols < (c+1)CH] -= Mw[...,chunk c] @ bm[chunk c, :]
        mma_nn<<<dim3(c + 1, NCHUNK - 1 - c, NH), 256, SMNN>>>(
            Mw + (size_t)(c + 1) * CH * TT + (size_t)c * CH,
            bm + (size_t)c * CH * TT,
            bm + (size_t)(c + 1) * CH * TT,
            CH, TT, TT, TT, TTTT, TTTT, TTTT, 1);
        chunk_solve<<<dim3((c + 2) * 16, NH), 256>>>(c + 1);
    }

    // A -= tril(QW) @ btil   (triangular k-range, subtract)
    mma_nn<<<gNT, 256, SMNN>>>(QW, bt, A, TT, TT, TT, TT, TTTT, TTTT, TTTT, 3);

    softmax_kernel<<<dim3(TT, NH), 256>>>();       // P in g_A (upper zeroed)

    // O = P @ V  split-K=4, partials into g_raw (free after prep)
    mma_nn<<<dim3(1, TT / BM, NH * 4), 256, SMNN>>>(
        A, v, raw, TT, TT, HD, DD, TTTT, (long long)TT * HD, HD, 8);
    reduce_pv<<<TT * DD / 1024, 256>>>();

    // out = O @ Wo
    mma_nn<<<dim3(DD / BN, TT / BM, 1), 256, SMNN>>>(O, Wo, out, DD, DD, DD, DD, 0, 0, 0, 0);
}